// round 16
// baseline (speedup 1.0000x reference)
#include <cuda_runtime.h>
#include <cuda_fp16.h>
#include <cstdint>
#include <cstddef>

#define TPB     640           // 16 MMA warps + 4 activation warps
#define MB      16
#define TSTEPS  512
#define ISZ     5
#define TI      (TSTEPS*ISZ)
#define HID     128
#define KTOT    144
#define KCH     9
#define WSTR    152           // halves per A row (304B: ldmatrix conflict-free)

#define B_BYTES   (512*WSTR*2)        // 155648
#define A_BYTES   (MB*WSTR*2)         // 4864 per buffer
#define GSTR      130                 // gates row stride in f32 words (8B-aligned pairs)
#define GPLANE    (16*GSTR)           // 2080 words per gate plane
#define G_BYTES   (4*GPLANE*4)        // 33280
#define SMEM_B    0
#define SMEM_A0   B_BYTES
#define SMEM_A1   (SMEM_A0 + A_BYTES)
#define SMEM_G    (SMEM_A1 + A_BYTES)
#define SMEM_TOTAL (SMEM_G + G_BYTES) // 198656

__device__ __forceinline__ uint32_t smem_u32(const void* p) {
    uint32_t a;
    asm("{ .reg .u64 t; cvta.to.shared.u64 t, %1; cvt.u32.u64 %0, t; }" : "=r"(a) : "l"(p));
    return a;
}
#define LDSM4(r0, r1, r2, r3, addr) \
    asm volatile("ldmatrix.sync.aligned.m8n8.x4.shared.b16 {%0,%1,%2,%3}, [%4];" \
        : "=r"(r0), "=r"(r1), "=r"(r2), "=r"(r3) : "r"(addr))
#define MMA16816(d, a0, a1, a2, a3, b0, b1) \
    asm volatile("mma.sync.aligned.m16n8k16.row.col.f32.f16.f16.f32 " \
        "{%0,%1,%2,%3}, {%4,%5,%6,%7}, {%8,%9}, {%0,%1,%2,%3};" \
        : "+f"((d)[0]), "+f"((d)[1]), "+f"((d)[2]), "+f"((d)[3]) \
        : "r"(a0), "r"(a1), "r"(a2), "r"(a3), "r"(b0), "r"(b1))
#define BAR_SYNC(id)   asm volatile("bar.sync %0, 640;"   :: "r"(id) : "memory")
#define BAR_ARRIVE(id) asm volatile("bar.arrive %0, 640;" :: "r"(id) : "memory")
#define MEMBAR_CTA()   asm volatile("membar.cta;" ::: "memory")

__device__ __forceinline__ float tanha(float x) {
    float r; asm("tanh.approx.f32 %0, %1;" : "=f"(r) : "f"(x)); return r;
}
__device__ __forceinline__ float siga(float x) {
    return fmaf(0.5f, tanha(0.5f * x), 0.5f);
}

__global__ void __launch_bounds__(TPB, 1)
lstm_hmma(const float* __restrict__ x,     const float* __restrict__ W_ih,
          const float* __restrict__ W_hh,  const float* __restrict__ b_ih,
          const float* __restrict__ b_hh,  const float* __restrict__ W_lin,
          const float* __restrict__ b_lin, float* __restrict__ out)
{
    extern __shared__ char smem[];
    const uint32_t sb = smem_u32(smem);
    const int tid = threadIdx.x;
    const int w = tid >> 5, l = tid & 31;
    const int q = l >> 2, m = l & 3;
    const int b0 = blockIdx.x * MB;

    // ---- stage B = W, fp16 [ni][k], ni = w*32 + g*8 + jj (gate = n8 tile) ----
    for (int e = tid; e < 512 * KTOT; e += TPB) {
        int ni = e / KTOT, k = e - ni * KTOT;
        int wb = ni >> 5, rem = ni & 31;
        int g = rem >> 3, jj = rem & 7;
        int nsrc = g * HID + wb * 8 + jj;
        float v = 0.f;
        if (k < HID)        v = W_hh[nsrc * HID + k];
        else if (k < 133)   v = W_ih[nsrc * ISZ + (k - HID)];
        else if (k == 133)  v = b_ih[nsrc] + b_hh[nsrc];
        *reinterpret_cast<__half*>(smem + SMEM_B + (size_t)(ni * WSTR + k) * 2) = __float2half(v);
    }
    __syncthreads();

    // ---- MMA warps: hoist B chunks 0..7 into regs (chunk 8 LDSM'd per step) ----
    uint32_t Bq[8][8];
    uint32_t b_lane = 0;
    if (w < 16) {
        b_lane = sb + SMEM_B +
            (uint32_t)(((32 * w + ((l >> 4) & 1) * 8 + (l & 7)) * WSTR + ((l >> 3) & 1) * 8) * 2);
        #pragma unroll
        for (int ch = 0; ch < 8; ch++) {
            LDSM4(Bq[ch][0], Bq[ch][1], Bq[ch][2], Bq[ch][3], b_lane + ch * 32);
            LDSM4(Bq[ch][4], Bq[ch][5], Bq[ch][6], Bq[ch][7],
                  b_lane + (uint32_t)(16 * WSTR * 2) + ch * 32);
        }
    }
    __syncthreads();

    // ---- init A buffers: zero, bias col (both), x(t=0) into buffer 0 ----
    for (int i = tid; i < 2 * A_BYTES / 4; i += TPB)
        reinterpret_cast<uint32_t*>(smem + SMEM_A0)[i] = 0u;
    __syncthreads();
    if (tid < MB) {
        *reinterpret_cast<__half*>(smem + SMEM_A0 + (tid * WSTR + 133) * 2) = __float2half(1.f);
        *reinterpret_cast<__half*>(smem + SMEM_A1 + (tid * WSTR + 133) * 2) = __float2half(1.f);
    }
    if (tid < MB * ISZ) {
        int r = tid / ISZ, i = tid - r * ISZ;
        *reinterpret_cast<__half*>(smem + SMEM_A0 + (r * WSTR + HID + i) * 2) =
            __float2half(x[(size_t)(b0 + r) * TI + i]);
    }
    __syncthreads();

    if (w < 16) {
        // ================= MMA warps =================
        const uint32_t a_lane0 = sb + SMEM_A0 +
            (uint32_t)(((((l >> 3) & 1) * 8 + (l & 7)) * WSTR + ((l >> 4) & 1) * 8) * 2);
        const uint32_t a_lane1 = a_lane0 + A_BYTES;
        float2* Gv = reinterpret_cast<float2*>(smem + SMEM_G);  // [4][16][GSTR/2]
        const int gc0 = 65 * q + 4 * w + m;          // float2 idx, row q
        const int gc1 = 65 * (q + 8) + 4 * w + m;    // row q+8

        for (int t = 0; t < TSTEPS; t++) {
            const uint32_t Ard = (t & 1) ? a_lane1 : a_lane0;
            float Ci[4], Cf[4], Cg[4], Co[4];
            #pragma unroll
            for (int u = 0; u < 4; u++) { Ci[u]=0.f; Cf[u]=0.f; Cg[u]=0.f; Co[u]=0.f; }

            #pragma unroll
            for (int cp = 0; cp < 4; cp++) {
                BAR_SYNC(1 + cp);                 // h cols 32cp..32cp+31 ready
                #pragma unroll
                for (int hh = 0; hh < 2; hh++) {
                    const int ch = 2 * cp + hh;
                    uint32_t a0, a1, a2, a3;
                    LDSM4(a0, a1, a2, a3, Ard + ch * 32);
                    MMA16816(Ci, a0, a1, a2, a3, Bq[ch][0], Bq[ch][1]);
                    MMA16816(Cf, a0, a1, a2, a3, Bq[ch][2], Bq[ch][3]);
                    MMA16816(Cg, a0, a1, a2, a3, Bq[ch][4], Bq[ch][5]);
                    MMA16816(Co, a0, a1, a2, a3, Bq[ch][6], Bq[ch][7]);
                }
            }
            BAR_SYNC(5);                          // x/bias chunk ready
            {
                uint32_t b80, b81, b82, b83, b84, b85, b86, b87;
                LDSM4(b80, b81, b82, b83, b_lane + 8 * 32);
                LDSM4(b84, b85, b86, b87, b_lane + (uint32_t)(16 * WSTR * 2) + 8 * 32);
                uint32_t a0, a1, a2, a3;
                LDSM4(a0, a1, a2, a3, Ard + 8 * 32);
                MMA16816(Ci, a0, a1, a2, a3, b80, b81);
                MMA16816(Cf, a0, a1, a2, a3, b82, b83);
                MMA16816(Cg, a0, a1, a2, a3, b84, b85);
                MMA16816(Co, a0, a1, a2, a3, b86, b87);
            }
            // publish gates (f32, exact)
            Gv[0 * 1040 + gc0] = make_float2(Ci[0], Ci[1]);
            Gv[0 * 1040 + gc1] = make_float2(Ci[2], Ci[3]);
            Gv[1 * 1040 + gc0] = make_float2(Cf[0], Cf[1]);
            Gv[1 * 1040 + gc1] = make_float2(Cf[2], Cf[3]);
            Gv[2 * 1040 + gc0] = make_float2(Cg[0], Cg[1]);
            Gv[2 * 1040 + gc1] = make_float2(Cg[2], Cg[3]);
            Gv[3 * 1040 + gc0] = make_float2(Co[0], Co[1]);
            Gv[3 * 1040 + gc1] = make_float2(Co[2], Co[3]);
            MEMBAR_CTA();
            BAR_ARRIVE(6);                        // gates(t) ready
        }
    } else {
        // ================= activation warps =================
        const int a  = tid - 512;                 // 0..127
        const int ar = a >> 3, as = a & 7;        // row, col-octet
        const float* G = reinterpret_cast<const float*>(smem + SMEM_G);
        const bool xduty = (a < MB * ISZ);
        const int xr = a / ISZ, xi = a - xr * ISZ;

        float c_st[16];
        #pragma unroll
        for (int u = 0; u < 16; u++) c_st[u] = 0.f;

        // prologue: buffer 0 contents (h=0, x(0), bias) count as produced for t=0
        BAR_ARRIVE(1); BAR_ARRIVE(2); BAR_ARRIVE(3); BAR_ARRIVE(4); BAR_ARRIVE(5);

        for (int t = 0; t < TSTEPS; t++) {
            float xv = 0.f;
            const bool dox = xduty && (t + 1 < TSTEPS);
            if (dox) xv = x[(size_t)(b0 + xr) * TI + (size_t)(t + 1) * ISZ + xi];

            BAR_SYNC(6);                          // gates(t) ready
            char* Awb = smem + SMEM_A0 + (((t + 1) & 1) ? A_BYTES : 0);

            #pragma unroll
            for (int cp = 0; cp < 4; cp++) {
                float h4[4];
                #pragma unroll
                for (int jj = 0; jj < 4; jj++) {
                    const int j = 32 * cp + 4 * as + jj;
                    const int base = GSTR * ar + j;
                    float gi = G[base];
                    float gf = G[base + GPLANE];
                    float gg = G[base + 2 * GPLANE];
                    float go = G[base + 3 * GPLANE];
                    const int u = cp * 4 + jj;
                    float cc = fmaf(siga(gf), c_st[u], siga(gi) * tanha(gg));
                    c_st[u] = cc;
                    h4[jj] = siga(go) * tanha(cc);
                }
                __half2 p0 = __floats2half2_rn(h4[0], h4[1]);
                __half2 p1 = __floats2half2_rn(h4[2], h4[3]);
                uint2 pv;
                pv.x = *reinterpret_cast<uint32_t*>(&p0);
                pv.y = *reinterpret_cast<uint32_t*>(&p1);
                *reinterpret_cast<uint2*>(Awb + ar * (WSTR * 2) + (32 * cp + 4 * as) * 2) = pv;
                MEMBAR_CTA();
                if (t < TSTEPS - 1) BAR_ARRIVE(1 + cp);
            }
            if (dox)
                *reinterpret_cast<__half*>(Awb + xr * (WSTR * 2) + (HID + xi) * 2) =
                    __float2half_rn(xv);
            MEMBAR_CTA();
            if (t < TSTEPS - 1) BAR_ARRIVE(5);
        }
    }

    __syncthreads();
    // ---- epilogue: final h(511) is in buffer 0 ----
    if (tid < 128) {
        const int row = tid >> 3, seg = tid & 7;
        const __half* Hf = reinterpret_cast<const __half*>(smem + SMEM_A0);
        float s = 0.f;
        #pragma unroll
        for (int jj = 0; jj < 16; jj++) {
            int j = seg * 16 + jj;
            s += __half2float(Hf[row * WSTR + j]) * W_lin[j];
        }
        s += __shfl_xor_sync(0xffffffffu, s, 4);
        s += __shfl_xor_sync(0xffffffffu, s, 2);
        s += __shfl_xor_sync(0xffffffffu, s, 1);
        if (seg == 0) out[b0 + row] = s + b_lin[0];
    }
}

extern "C" void kernel_launch(void* const* d_in, const int* in_sizes, int n_in,
                              void* d_out, int out_size) {
    const float* x     = (const float*)d_in[0];
    const float* W_ih  = (const float*)d_in[1];
    const float* W_hh  = (const float*)d_in[2];
    const float* b_ih  = (const float*)d_in[3];
    const float* b_hh  = (const float*)d_in[4];
    const float* W_lin = (const float*)d_in[5];
    const float* b_lin = (const float*)d_in[6];
    float* out = (float*)d_out;

    int B    = in_sizes[0] / TI;   // 2048
    int nCTA = B / MB;             // 128 CTAs, one wave

    cudaFuncSetAttribute(lstm_hmma,
                         cudaFuncAttributeMaxDynamicSharedMemorySize, SMEM_TOTAL);
    lstm_hmma<<<nCTA, TPB, SMEM_TOTAL>>>(x, W_ih, W_hh, b_ih, b_hh,
                                         W_lin, b_lin, out);
}